// round 4
// baseline (speedup 1.0000x reference)
#include <cuda_runtime.h>
#include <cstdint>
#include <cstddef>

#define DIM_K 4096      // in_features
#define DIM_N 4096      // out_features
#define DIM_M 8192      // B*S

#define QMAX 16250.0f   // 15-bit quant range (keeps hi digit <= 127 after rounding)

// ---------------- scratch (static device arrays; no allocation) ----------------
__device__ __align__(256) float g_cn[DIM_K];             // column L1 norms
__device__ __align__(256) float g_mask[DIM_K];           // 1.0 = binarized column
__device__ float g_nbin;
__device__ int g_xmax_i, g_wmax_i;                       // float-bit maxes (>=0)
__device__ __align__(256) float  g_wbin[(size_t)DIM_N * DIM_K];   // fp32 w_bin
__device__ __align__(256) int8_t g_xa[(size_t)DIM_M * DIM_K];     // x hi digit
__device__ __align__(256) int8_t g_xb[(size_t)DIM_M * DIM_K];     // x lo digit
__device__ __align__(256) int8_t g_wa[(size_t)DIM_N * DIM_K];     // w hi digit
__device__ __align__(256) int8_t g_wb[(size_t)DIM_N * DIM_K];     // w lo digit

__device__ __forceinline__ uint32_t smem_u32(const void* p) {
    uint32_t a;
    asm("{ .reg .u64 t; cvta.to.shared.u64 t, %1; cvt.u32.u64 %0, t; }" : "=r"(a) : "l"(p));
    return a;
}

// ================= preprocessing =================

// Strict sequential fp32 column L1 norms (bit-identical order to passing version).
__global__ void k_colnorm(const float* __restrict__ w) {
    if (blockIdx.x == 0 && threadIdx.x == 0) { g_xmax_i = 0; g_wmax_i = 0; }
    int j = blockIdx.x * 64 + threadIdx.x;
    const float* p = w + j;
    float s = 0.f;
    for (int i = 0; i < DIM_K; i += 32) {
        float v[32];
#pragma unroll
        for (int u = 0; u < 32; ++u) v[u] = fabsf(p[(size_t)(i + u) * DIM_K]);
#pragma unroll
        for (int u = 0; u < 32; ++u) s += v[u];
    }
    g_cn[j] = s;
}

// Single block: bitonic sort, quantiles, band mask, n_bin.
__global__ void k_quant() {
    __shared__ float s_sorted[DIM_K];
    __shared__ float s_lo, s_hi;
    __shared__ int s_cnt;
    int t = threadIdx.x;  // 1024 threads

#pragma unroll
    for (int c = 0; c < 4; ++c) s_sorted[c * 1024 + t] = g_cn[c * 1024 + t];
    if (t == 0) s_cnt = 0;
    __syncthreads();

    for (int k = 2; k <= DIM_K; k <<= 1) {
        for (int jj = k >> 1; jj > 0; jj >>= 1) {
#pragma unroll
            for (int c = 0; c < 4; ++c) {
                int i = c * 1024 + t;
                int ixj = i ^ jj;
                if (ixj > i) {
                    float a = s_sorted[i], b = s_sorted[ixj];
                    bool up = ((i & k) == 0);
                    if ((a > b) == up) { s_sorted[i] = b; s_sorted[ixj] = a; }
                }
            }
            __syncthreads();
        }
    }

    if (t == 0) {
        // jnp.quantile 'linear': 0.05*4095 = 204.75; 0.95*4095 = 3890.25
        s_lo = s_sorted[204]  + 0.75f * (s_sorted[205]  - s_sorted[204]);
        s_hi = s_sorted[3890] + 0.25f * (s_sorted[3891] - s_sorted[3890]);
    }
    __syncthreads();

    int local = 0;
#pragma unroll
    for (int c = 0; c < 4; ++c) {
        int j = c * 1024 + t;
        float v = g_cn[j];
        bool band = (v > s_lo) && (v < s_hi);   // middle band
        float m = band ? 0.f : 1.f;             // binarized = ~band
        g_mask[j] = m;
        local += (int)m;
    }
    atomicAdd(&s_cnt, local);
    __syncthreads();
    if (t == 0) g_nbin = (float)s_cnt;
}

// Per row: scale = sum(|w|*mask)/n_bin; w_bin = mask ? w*scale : w. Track max|w_bin|.
__global__ void k_wbin(const float* __restrict__ w) {
    __shared__ float red[256];
    __shared__ float s_scale;
    int r = blockIdx.x, t = threadIdx.x;
    const float* wr = w + (size_t)r * DIM_K;

    float s = 0.f;
    for (int j = t; j < DIM_K; j += 256) s += fabsf(wr[j]) * g_mask[j];
    red[t] = s;
    __syncthreads();
    for (int o = 128; o > 0; o >>= 1) {
        if (t < o) red[t] += red[t + o];
        __syncthreads();
    }
    if (t == 0) s_scale = red[0] / g_nbin;
    __syncthreads();
    float scale = s_scale;

    float* dst = g_wbin + (size_t)r * DIM_K;
    float mx = 0.f;
    for (int j = t; j < DIM_K; j += 256) {
        float v = wr[j];
        float o = (g_mask[j] != 0.f) ? v * scale : v;
        dst[j] = o;
        mx = fmaxf(mx, fabsf(o));
    }
#pragma unroll
    for (int o = 16; o > 0; o >>= 1) mx = fmaxf(mx, __shfl_xor_sync(0xFFFFFFFFu, mx, o));
    if ((t & 31) == 0) atomicMax(&g_wmax_i, __float_as_int(mx));
}

// Global max|x|.
__global__ void k_xmax(const float* __restrict__ x) {
    size_t i0 = ((size_t)blockIdx.x * 256 + threadIdx.x) * 16;
    float mx = 0.f;
#pragma unroll
    for (int u = 0; u < 16; u += 4) {
        float4 v = *(const float4*)(x + i0 + u);
        mx = fmaxf(mx, fmaxf(fmaxf(fabsf(v.x), fabsf(v.y)), fmaxf(fabsf(v.z), fabsf(v.w))));
    }
#pragma unroll
    for (int o = 16; o > 0; o >>= 1) mx = fmaxf(mx, __shfl_xor_sync(0xFFFFFFFFu, mx, o));
    if ((threadIdx.x & 31) == 0) atomicMax(&g_xmax_i, __float_as_int(mx));
}

// Quantize src (fp32) to 2-digit int8 planes: v_int = round(v*S); a=(v_int+64)>>7; b=v_int-(a<<7).
__device__ __forceinline__ void quant16(const float* src, int8_t* pa, int8_t* pb,
                                        size_t i0, float S) {
    char4 av[4], bv[4];
#pragma unroll
    for (int u = 0; u < 4; ++u) {
        float4 v = *(const float4*)(src + i0 + u * 4);
        int xi, a, b;
        char aa[4], bb[4];
        float f[4] = {v.x, v.y, v.z, v.w};
#pragma unroll
        for (int e = 0; e < 4; ++e) {
            xi = __float2int_rn(f[e] * S);
            a = (xi + 64) >> 7;
            b = xi - (a << 7);
            aa[e] = (char)a; bb[e] = (char)b;
        }
        av[u] = make_char4(aa[0], aa[1], aa[2], aa[3]);
        bv[u] = make_char4(bb[0], bb[1], bb[2], bb[3]);
    }
    *(int4*)(pa + i0) = *(int4*)av;
    *(int4*)(pb + i0) = *(int4*)bv;
}

__global__ void k_xquant(const float* __restrict__ x) {
    float S = QMAX / __int_as_float(g_xmax_i);
    size_t i0 = ((size_t)blockIdx.x * 256 + threadIdx.x) * 16;
    quant16(x, g_xa, g_xb, i0, S);
}
__global__ void k_wquant() {
    float S = QMAX / __int_as_float(g_wmax_i);
    size_t i0 = ((size_t)blockIdx.x * 256 + threadIdx.x) * 16;
    quant16(g_wbin, g_wa, g_wb, i0, S);
}

// ================= GEMM: int8 dual-digit IMMA =================
// CTA 128x128, BK=64. Smem row = 128B: [a-digit 64B | b-digit 64B], SW128 swizzle.
// 8 warps (2M x 4N), warp tile 64x32. 3-stage cp.async.
#define BM 128
#define BN 128
#define BK 64
#define KTILES (DIM_K / BK)         // 64
#define STAGES 3
#define A_BYTES 16384               // 128 rows x 128B
#define B_BYTES 16384
#define STAGE_BYTES (A_BYTES + B_BYTES)
#define GEMM_SMEM (STAGES * STAGE_BYTES)

__device__ __forceinline__ void cp16(uint32_t dst, const void* src) {
    asm volatile("cp.async.cg.shared.global [%0], [%1], 16;" :: "r"(dst), "l"(src));
}
__device__ __forceinline__ void ldm_x4(uint32_t* r, uint32_t addr) {
    asm volatile("ldmatrix.sync.aligned.m8n8.x4.shared.b16 {%0,%1,%2,%3}, [%4];"
                 : "=r"(r[0]), "=r"(r[1]), "=r"(r[2]), "=r"(r[3]) : "r"(addr));
}
__device__ __forceinline__ void imma(int* c, const uint32_t* a, uint32_t b0, uint32_t b1) {
    asm volatile(
        "mma.sync.aligned.m16n8k32.row.col.s32.s8.s8.s32 "
        "{%0,%1,%2,%3}, {%4,%5,%6,%7}, {%8,%9}, {%0,%1,%2,%3};"
        : "+r"(c[0]), "+r"(c[1]), "+r"(c[2]), "+r"(c[3])
        : "r"(a[0]), "r"(a[1]), "r"(a[2]), "r"(a[3]), "r"(b0), "r"(b1));
}

__global__ void __launch_bounds__(256, 1) k_gemm(
    const float* __restrict__ bias, float* __restrict__ out)
{
    extern __shared__ char smem[];
    const uint32_t sb = smem_u32(smem);
    const int tid = threadIdx.x;
    const int wid = tid >> 5;
    const int lane = tid & 31;
    const int warp_m = wid & 1;    // 0..1 -> M offset 64
    const int warp_n = wid >> 1;   // 0..3 -> N offset 32
    const int ntile = blockIdx.x;
    const int mtile = blockIdx.y;

    // loaders: 8 threads per 128B smem row; lc<4 -> a-plane chunks, lc>=4 -> b-plane
    const int lrow = tid >> 3;          // 0..31
    const int lc   = tid & 7;
    const int8_t* gA = ((lc < 4) ? g_xa : g_xb) + (size_t)mtile * BM * DIM_K;
    const int8_t* gB = ((lc < 4) ? g_wa : g_wb) + (size_t)ntile * BN * DIM_K;
    const int goff = (lc & 3) * 16;     // byte offset within 64B digit chunk
    const int soff = lc * 16;           // byte offset within 128B smem row
    uint32_t swz[4];
#pragma unroll
    for (int p = 0; p < 4; ++p) {
        int row = lrow + p * 32;
        swz[p] = (uint32_t)(row * 128 + (soff ^ ((row & 7) << 4)));
    }

    // ldmatrix lane addressing
    const uint32_t sx = (uint32_t)((lane & 7) << 4);
    const int arow = warp_m * 64 + (lane & 15);                          // + mt*16
    const uint32_t acol16 = (lane & 16) ? 16u : 0u;
    const int brow = warp_n * 32 + (lane & 7) + ((lane & 16) ? 8 : 0);   // + p*16
    const uint32_t bcol16 = (lane & 8) ? 16u : 0u;

    int P[4][4][4], Q[4][4][4], R[4][4][4];
#pragma unroll
    for (int i = 0; i < 4; ++i)
#pragma unroll
        for (int j = 0; j < 4; ++j)
#pragma unroll
            for (int k = 0; k < 4; ++k) { P[i][j][k] = 0; Q[i][j][k] = 0; R[i][j][k] = 0; }

    auto load_stage = [&](int s, int kt) {
        uint32_t sA = sb + s * STAGE_BYTES;
        uint32_t sB = sA + A_BYTES;
#pragma unroll
        for (int p = 0; p < 4; ++p) {
            int row = lrow + p * 32;
            cp16(sA + swz[p], gA + (size_t)row * DIM_K + kt * BK + goff);
        }
#pragma unroll
        for (int p = 0; p < 4; ++p) {
            int row = lrow + p * 32;
            cp16(sB + swz[p], gB + (size_t)row * DIM_K + kt * BK + goff);
        }
    };

#pragma unroll
    for (int s = 0; s < STAGES - 1; ++s) {
        load_stage(s, s);
        asm volatile("cp.async.commit_group;" ::: "memory");
    }

    for (int kt = 0; kt < KTILES; ++kt) {
        asm volatile("cp.async.wait_group 1;" ::: "memory");
        __syncthreads();

        if (kt + STAGES - 1 < KTILES) load_stage((kt + STAGES - 1) % STAGES, kt + STAGES - 1);
        asm volatile("cp.async.commit_group;" ::: "memory");

        const int s = kt % STAGES;
        const uint32_t sA = sb + s * STAGE_BYTES;
        const uint32_t sB = sA + A_BYTES;

#pragma unroll
        for (int ks = 0; ks < 2; ++ks) {
            // B fragments: 4 nt (32 N), both digits
            uint32_t ba[8], bb[8];
#pragma unroll
            for (int p = 0; p < 2; ++p) {
                uint32_t rb = sB + (uint32_t)((brow + p * 16) * 128);
                ldm_x4(ba + 4 * p, rb + (((uint32_t)(ks * 32) + bcol16) ^ sx));
                ldm_x4(bb + 4 * p, rb + (((uint32_t)(64 + ks * 32) + bcol16) ^ sx));
            }
#pragma unroll
            for (int mt = 0; mt < 4; ++mt) {
                uint32_t aa[4], ab[4];
                uint32_t ra = sA + (uint32_t)((arow + mt * 16) * 128);
                ldm_x4(aa, ra + (((uint32_t)(ks * 32) + acol16) ^ sx));
                ldm_x4(ab, ra + (((uint32_t)(64 + ks * 32) + acol16) ^ sx));
#pragma unroll
                for (int nt = 0; nt < 4; ++nt) {
                    imma(P[mt][nt], aa, ba[2 * nt], ba[2 * nt + 1]);
                    imma(Q[mt][nt], aa, bb[2 * nt], bb[2 * nt + 1]);
                    imma(Q[mt][nt], ab, ba[2 * nt], ba[2 * nt + 1]);
                    imma(R[mt][nt], ab, bb[2 * nt], bb[2 * nt + 1]);
                }
            }
        }
    }

    // ---- epilogue: combine digits, scale, add bias ----
    const float invS = (__int_as_float(g_xmax_i) / QMAX) * (__int_as_float(g_wmax_i) / QMAX);
    const int obase_n = ntile * BN + warp_n * 32;
    float bv0[4], bv1[4];
#pragma unroll
    for (int nt = 0; nt < 4; ++nt) {
        int col = obase_n + nt * 8 + (lane & 3) * 2;
        bv0[nt] = __ldg(bias + col);
        bv1[nt] = __ldg(bias + col + 1);
    }
#pragma unroll
    for (int mt = 0; mt < 4; ++mt) {
        int row0 = mtile * BM + warp_m * 64 + mt * 16 + (lane >> 2);
#pragma unroll
        for (int nt = 0; nt < 4; ++nt) {
            int col = obase_n + nt * 8 + (lane & 3) * 2;
            float v[4];
#pragma unroll
            for (int e = 0; e < 4; ++e)
                v[e] = (16384.f * (float)P[mt][nt][e] + 128.f * (float)Q[mt][nt][e]
                        + (float)R[mt][nt][e]) * invS;
            float2 o0 = make_float2(v[0] + bv0[nt], v[1] + bv1[nt]);
            float2 o1 = make_float2(v[2] + bv0[nt], v[3] + bv1[nt]);
            *(float2*)(out + (size_t)row0 * DIM_N + col) = o0;
            *(float2*)(out + (size_t)(row0 + 8) * DIM_N + col) = o1;
        }
    }
}

// ================= launch =================
extern "C" void kernel_launch(void* const* d_in, const int* in_sizes, int n_in,
                              void* d_out, int out_size) {
    const float* x    = (const float*)d_in[0];   // [8192, 4096]
    const float* w    = (const float*)d_in[1];   // [4096, 4096]
    const float* bias = (const float*)d_in[2];   // [4096]
    float* out = (float*)d_out;                  // [8192, 4096]

    cudaFuncSetAttribute(k_gemm, cudaFuncAttributeMaxDynamicSharedMemorySize, GEMM_SMEM);

    k_colnorm<<<DIM_K / 64, 64>>>(w);
    k_quant<<<1, 1024>>>();
    k_wbin<<<DIM_N, 256>>>(w);
    k_xmax<<<(size_t)DIM_M * DIM_K / (256 * 16), 256>>>(x);
    k_wquant<<<(size_t)DIM_N * DIM_K / (256 * 16), 256>>>();
    k_xquant<<<(size_t)DIM_M * DIM_K / (256 * 16), 256>>>(x);
    k_gemm<<<dim3(DIM_N / BN, DIM_M / BM), 256, GEMM_SMEM>>>(bias, out);
}

// round 5
// speedup vs baseline: 1.3249x; 1.3249x over previous
#include <cuda_runtime.h>
#include <cstdint>
#include <cstddef>

#define DIM_K 4096      // in_features
#define DIM_N 4096      // out_features
#define DIM_M 8192      // B*S

#define QMAX 16250.0f   // 15-bit quant range (hi digit <= 127 after rounding)

// ---------------- scratch (static device arrays; no allocation) ----------------
__device__ __align__(256) float g_cn[DIM_K];             // column L1 norms
__device__ __align__(256) float g_mask[DIM_K];           // 1.0 = binarized column
__device__ float g_nbin;
__device__ __align__(256) float g_xs[DIM_M];             // per-row x scale (rowmax/QMAX)
__device__ __align__(256) float g_ws[DIM_N];             // per-row w scale
__device__ __align__(256) int8_t g_xa[(size_t)DIM_M * DIM_K];   // x hi digit
__device__ __align__(256) int8_t g_xb[(size_t)DIM_M * DIM_K];   // x lo digit
__device__ __align__(256) int8_t g_wa[(size_t)DIM_N * DIM_K];   // w hi digit
__device__ __align__(256) int8_t g_wb[(size_t)DIM_N * DIM_K];   // w lo digit

__device__ __forceinline__ uint32_t smem_u32(const void* p) {
    uint32_t a;
    asm("{ .reg .u64 t; cvta.to.shared.u64 t, %1; cvt.u32.u64 %0, t; }" : "=r"(a) : "l"(p));
    return a;
}

// ================= preprocessing =================

// Strict sequential fp32 column L1 norms (bit-identical order to passing version).
__global__ void k_colnorm(const float* __restrict__ w) {
    int j = blockIdx.x * 64 + threadIdx.x;
    const float* p = w + j;
    float s = 0.f;
    for (int i = 0; i < DIM_K; i += 32) {
        float v[32];
#pragma unroll
        for (int u = 0; u < 32; ++u) v[u] = fabsf(p[(size_t)(i + u) * DIM_K]);
#pragma unroll
        for (int u = 0; u < 32; ++u) s += v[u];
    }
    g_cn[j] = s;
}

// Single block: bitonic sort, quantiles, band mask, n_bin.
__global__ void k_quant() {
    __shared__ float s_sorted[DIM_K];
    __shared__ float s_lo, s_hi;
    __shared__ int s_cnt;
    int t = threadIdx.x;  // 1024 threads

#pragma unroll
    for (int c = 0; c < 4; ++c) s_sorted[c * 1024 + t] = g_cn[c * 1024 + t];
    if (t == 0) s_cnt = 0;
    __syncthreads();

    for (int k = 2; k <= DIM_K; k <<= 1) {
        for (int jj = k >> 1; jj > 0; jj >>= 1) {
#pragma unroll
            for (int c = 0; c < 4; ++c) {
                int i = c * 1024 + t;
                int ixj = i ^ jj;
                if (ixj > i) {
                    float a = s_sorted[i], b = s_sorted[ixj];
                    bool up = ((i & k) == 0);
                    if ((a > b) == up) { s_sorted[i] = b; s_sorted[ixj] = a; }
                }
            }
            __syncthreads();
        }
    }

    if (t == 0) {
        // jnp.quantile 'linear': 0.05*4095 = 204.75; 0.95*4095 = 3890.25
        s_lo = s_sorted[204]  + 0.75f * (s_sorted[205]  - s_sorted[204]);
        s_hi = s_sorted[3890] + 0.25f * (s_sorted[3891] - s_sorted[3890]);
    }
    __syncthreads();

    int local = 0;
#pragma unroll
    for (int c = 0; c < 4; ++c) {
        int j = c * 1024 + t;
        float v = g_cn[j];
        bool band = (v > s_lo) && (v < s_hi);   // middle band
        float m = band ? 0.f : 1.f;             // binarized = ~band
        g_mask[j] = m;
        local += (int)m;
    }
    atomicAdd(&s_cnt, local);
    __syncthreads();
    if (t == 0) g_nbin = (float)s_cnt;
}

// helpers: block reductions (256 threads)
__device__ __forceinline__ float blk_sum(float v, float* red, int t) {
    red[t] = v; __syncthreads();
    for (int o = 128; o > 0; o >>= 1) { if (t < o) red[t] += red[t + o]; __syncthreads(); }
    float r = red[0]; __syncthreads(); return r;
}
__device__ __forceinline__ float blk_max(float v, float* red, int t) {
    red[t] = v; __syncthreads();
    for (int o = 128; o > 0; o >>= 1) { if (t < o) red[t] = fmaxf(red[t], red[t + o]); __syncthreads(); }
    float r = red[0]; __syncthreads(); return r;
}

// Per w-row: scale = sum(|w|*mask)/n_bin; o = mask ? w*scale : w;
// rowmax -> per-row quant scale; emit 2-digit int8 planes.
__global__ void k_wbinq(const float* __restrict__ w) {
    __shared__ float red[256];
    int r = blockIdx.x, t = threadIdx.x;
    const float* wr = w + (size_t)r * DIM_K;

    float4 v4[4];
    float o[16];
#pragma unroll
    for (int c = 0; c < 4; ++c) v4[c] = *(const float4*)(wr + t * 4 + c * 1024);

    float s = 0.f;
#pragma unroll
    for (int c = 0; c < 4; ++c) {
        const float* f = (const float*)&v4[c];
#pragma unroll
        for (int e = 0; e < 4; ++e) s += fabsf(f[e]) * g_mask[t * 4 + c * 1024 + e];
    }
    float scale = blk_sum(s, red, t) / g_nbin;

    float mx = 0.f;
#pragma unroll
    for (int c = 0; c < 4; ++c) {
        const float* f = (const float*)&v4[c];
#pragma unroll
        for (int e = 0; e < 4; ++e) {
            int j = t * 4 + c * 1024 + e;
            float val = (g_mask[j] != 0.f) ? f[e] * scale : f[e];
            o[c * 4 + e] = val;
            mx = fmaxf(mx, fabsf(val));
        }
    }
    mx = blk_max(mx, red, t);
    if (t == 0) g_ws[r] = mx / QMAX;
    float S = QMAX / mx;

#pragma unroll
    for (int c = 0; c < 4; ++c) {
        char4 av, bv;
        char* ap = (char*)&av; char* bp = (char*)&bv;
#pragma unroll
        for (int e = 0; e < 4; ++e) {
            int xi = __float2int_rn(o[c * 4 + e] * S);
            int a = (xi + 64) >> 7;
            ap[e] = (char)a; bp[e] = (char)(xi - (a << 7));
        }
        size_t idx = (size_t)r * DIM_K + t * 4 + c * 1024;
        *(char4*)(g_wa + idx) = av;
        *(char4*)(g_wb + idx) = bv;
    }
}

// Per x-row: rowmax -> per-row scale; emit 2-digit int8 planes.
__global__ void k_xquant(const float* __restrict__ x) {
    __shared__ float red[256];
    int r = blockIdx.x, t = threadIdx.x;
    const float* xr = x + (size_t)r * DIM_K;

    float4 v4[4];
#pragma unroll
    for (int c = 0; c < 4; ++c) v4[c] = *(const float4*)(xr + t * 4 + c * 1024);

    float mx = 0.f;
#pragma unroll
    for (int c = 0; c < 4; ++c) {
        const float* f = (const float*)&v4[c];
#pragma unroll
        for (int e = 0; e < 4; ++e) mx = fmaxf(mx, fabsf(f[e]));
    }
    mx = blk_max(mx, red, t);
    if (t == 0) g_xs[r] = mx / QMAX;
    float S = QMAX / mx;

#pragma unroll
    for (int c = 0; c < 4; ++c) {
        const float* f = (const float*)&v4[c];
        char4 av, bv;
        char* ap = (char*)&av; char* bp = (char*)&bv;
#pragma unroll
        for (int e = 0; e < 4; ++e) {
            int xi = __float2int_rn(f[e] * S);
            int a = (xi + 64) >> 7;
            ap[e] = (char)a; bp[e] = (char)(xi - (a << 7));
        }
        size_t idx = (size_t)r * DIM_K + t * 4 + c * 1024;
        *(char4*)(g_xa + idx) = av;
        *(char4*)(g_xb + idx) = bv;
    }
}

// ================= GEMM: int8 dual-digit IMMA (P, Q only) =================
// CTA 128x128, BK=64. Smem row = 128B: [a-digit 64B | b-digit 64B], SW128 swizzle.
// 8 warps (2M x 4N), warp tile 64x32. 3-stage cp.async.
#define BM 128
#define BN 128
#define BK 64
#define KTILES (DIM_K / BK)         // 64
#define STAGES 3
#define A_BYTES 16384
#define B_BYTES 16384
#define STAGE_BYTES (A_BYTES + B_BYTES)
#define GEMM_SMEM (STAGES * STAGE_BYTES)

__device__ __forceinline__ void cp16(uint32_t dst, const void* src) {
    asm volatile("cp.async.cg.shared.global [%0], [%1], 16;" :: "r"(dst), "l"(src));
}
__device__ __forceinline__ void ldm_x4(uint32_t* r, uint32_t addr) {
    asm volatile("ldmatrix.sync.aligned.m8n8.x4.shared.b16 {%0,%1,%2,%3}, [%4];"
                 : "=r"(r[0]), "=r"(r[1]), "=r"(r[2]), "=r"(r[3]) : "r"(addr));
}
__device__ __forceinline__ void imma(int* c, const uint32_t* a, uint32_t b0, uint32_t b1) {
    asm volatile(
        "mma.sync.aligned.m16n8k32.row.col.s32.s8.s8.s32 "
        "{%0,%1,%2,%3}, {%4,%5,%6,%7}, {%8,%9}, {%0,%1,%2,%3};"
        : "+r"(c[0]), "+r"(c[1]), "+r"(c[2]), "+r"(c[3])
        : "r"(a[0]), "r"(a[1]), "r"(a[2]), "r"(a[3]), "r"(b0), "r"(b1));
}

__global__ void __launch_bounds__(256, 1) k_gemm(
    const float* __restrict__ bias, float* __restrict__ out)
{
    extern __shared__ char smem[];
    const uint32_t sb = smem_u32(smem);
    const int tid = threadIdx.x;
    const int wid = tid >> 5;
    const int lane = tid & 31;
    const int warp_m = wid & 1;    // 0..1 -> M offset 64
    const int warp_n = wid >> 1;   // 0..3 -> N offset 32
    const int ntile = blockIdx.x;
    const int mtile = blockIdx.y;

    // loaders: 8 threads per 128B smem row; lc<4 -> a-plane chunks, lc>=4 -> b-plane
    const int lrow = tid >> 3;          // 0..31
    const int lc   = tid & 7;
    const int8_t* gA = ((lc < 4) ? g_xa : g_xb) + (size_t)mtile * BM * DIM_K;
    const int8_t* gB = ((lc < 4) ? g_wa : g_wb) + (size_t)ntile * BN * DIM_K;
    const int goff = (lc & 3) * 16;
    const int soff = lc * 16;
    uint32_t swz[4];
#pragma unroll
    for (int p = 0; p < 4; ++p) {
        int row = lrow + p * 32;
        swz[p] = (uint32_t)(row * 128 + (soff ^ ((row & 7) << 4)));
    }

    // ldmatrix lane addressing
    const uint32_t sx = (uint32_t)((lane & 7) << 4);
    const int arow = warp_m * 64 + (lane & 15);                          // + mt*16
    const uint32_t acol16 = (lane & 16) ? 16u : 0u;
    const int brow = warp_n * 32 + (lane & 7) + ((lane & 16) ? 8 : 0);   // + p*16
    const uint32_t bcol16 = (lane & 8) ? 16u : 0u;

    int P[4][4][4], Q[4][4][4];
#pragma unroll
    for (int i = 0; i < 4; ++i)
#pragma unroll
        for (int j = 0; j < 4; ++j)
#pragma unroll
            for (int k = 0; k < 4; ++k) { P[i][j][k] = 0; Q[i][j][k] = 0; }

    auto load_stage = [&](int s, int kt) {
        uint32_t sA = sb + s * STAGE_BYTES;
        uint32_t sB = sA + A_BYTES;
#pragma unroll
        for (int p = 0; p < 4; ++p) {
            int row = lrow + p * 32;
            cp16(sA + swz[p], gA + (size_t)row * DIM_K + kt * BK + goff);
        }
#pragma unroll
        for (int p = 0; p < 4; ++p) {
            int row = lrow + p * 32;
            cp16(sB + swz[p], gB + (size_t)row * DIM_K + kt * BK + goff);
        }
    };

#pragma unroll
    for (int s = 0; s < STAGES - 1; ++s) {
        load_stage(s, s);
        asm volatile("cp.async.commit_group;" ::: "memory");
    }

    for (int kt = 0; kt < KTILES; ++kt) {
        asm volatile("cp.async.wait_group 1;" ::: "memory");
        __syncthreads();

        if (kt + STAGES - 1 < KTILES) load_stage((kt + STAGES - 1) % STAGES, kt + STAGES - 1);
        asm volatile("cp.async.commit_group;" ::: "memory");

        const int s = kt % STAGES;
        const uint32_t sA = sb + s * STAGE_BYTES;
        const uint32_t sB = sA + A_BYTES;

#pragma unroll
        for (int ks = 0; ks < 2; ++ks) {
            uint32_t ba[8], bb[8];
#pragma unroll
            for (int p = 0; p < 2; ++p) {
                uint32_t rb = sB + (uint32_t)((brow + p * 16) * 128);
                ldm_x4(ba + 4 * p, rb + (((uint32_t)(ks * 32) + bcol16) ^ sx));
                ldm_x4(bb + 4 * p, rb + (((uint32_t)(64 + ks * 32) + bcol16) ^ sx));
            }
#pragma unroll
            for (int mt = 0; mt < 4; ++mt) {
                uint32_t aa[4], ab[4];
                uint32_t ra = sA + (uint32_t)((arow + mt * 16) * 128);
                ldm_x4(aa, ra + (((uint32_t)(ks * 32) + acol16) ^ sx));
                ldm_x4(ab, ra + (((uint32_t)(64 + ks * 32) + acol16) ^ sx));
#pragma unroll
                for (int nt = 0; nt < 4; ++nt) {
                    imma(P[mt][nt], aa, ba[2 * nt], ba[2 * nt + 1]);   // a*c
                    imma(Q[mt][nt], aa, bb[2 * nt], bb[2 * nt + 1]);   // a*d
                    imma(Q[mt][nt], ab, ba[2 * nt], ba[2 * nt + 1]);   // b*c
                }
            }
        }
    }

    // ---- epilogue: combine digits, per-row scales, bias ----
    const int obase_n = ntile * BN + warp_n * 32;
    float bv0[4], bv1[4], ws0[4], ws1[4];
#pragma unroll
    for (int nt = 0; nt < 4; ++nt) {
        int col = obase_n + nt * 8 + (lane & 3) * 2;
        bv0[nt] = __ldg(bias + col);
        bv1[nt] = __ldg(bias + col + 1);
        ws0[nt] = __ldg(g_ws + col);
        ws1[nt] = __ldg(g_ws + col + 1);
    }
#pragma unroll
    for (int mt = 0; mt < 4; ++mt) {
        int row0 = mtile * BM + warp_m * 64 + mt * 16 + (lane >> 2);
        float xs0 = __ldg(g_xs + row0);
        float xs1 = __ldg(g_xs + row0 + 8);
#pragma unroll
        for (int nt = 0; nt < 4; ++nt) {
            int col = obase_n + nt * 8 + (lane & 3) * 2;
            float v0 = (16384.f * (float)P[mt][nt][0] + 128.f * (float)Q[mt][nt][0]);
            float v1 = (16384.f * (float)P[mt][nt][1] + 128.f * (float)Q[mt][nt][1]);
            float v2 = (16384.f * (float)P[mt][nt][2] + 128.f * (float)Q[mt][nt][2]);
            float v3 = (16384.f * (float)P[mt][nt][3] + 128.f * (float)Q[mt][nt][3]);
            float2 o0 = make_float2(v0 * (xs0 * ws0[nt]) + bv0[nt],
                                    v1 * (xs0 * ws1[nt]) + bv1[nt]);
            float2 o1 = make_float2(v2 * (xs1 * ws0[nt]) + bv0[nt],
                                    v3 * (xs1 * ws1[nt]) + bv1[nt]);
            *(float2*)(out + (size_t)row0 * DIM_N + col) = o0;
            *(float2*)(out + (size_t)(row0 + 8) * DIM_N + col) = o1;
        }
    }
}

// ================= launch =================
extern "C" void kernel_launch(void* const* d_in, const int* in_sizes, int n_in,
                              void* d_out, int out_size) {
    const float* x    = (const float*)d_in[0];   // [8192, 4096]
    const float* w    = (const float*)d_in[1];   // [4096, 4096]
    const float* bias = (const float*)d_in[2];   // [4096]
    float* out = (float*)d_out;                  // [8192, 4096]

    cudaFuncSetAttribute(k_gemm, cudaFuncAttributeMaxDynamicSharedMemorySize, GEMM_SMEM);

    k_colnorm<<<DIM_K / 64, 64>>>(w);
    k_quant<<<1, 1024>>>();
    k_wbinq<<<DIM_N, 256>>>(w);
    k_xquant<<<DIM_M, 256>>>(x);
    k_gemm<<<dim3(DIM_N / BN, DIM_M / BM), 256, GEMM_SMEM>>>(bias, out);
}

// round 6
// speedup vs baseline: 9.2290x; 6.9660x over previous
#include <cuda_runtime.h>
#include <cuda_fp16.h>
#include <cstdint>
#include <cstddef>

#define DIM_K 4096      // in_features
#define DIM_N 4096      // out_features
#define DIM_M 8192      // B*S

// ---------------- scratch (static device arrays; no allocation) ----------------
__device__ __align__(256) float g_cn[DIM_K];             // column L1 norms
__device__ __align__(256) float g_mask[DIM_K];           // 1.0 = binarized column
__device__ float g_nbin;
__device__ __align__(256) __half g_xh[(size_t)DIM_M * DIM_K];   // fp16 x
__device__ __align__(256) __half g_wh[(size_t)DIM_N * DIM_K];   // fp16 w_bin

__device__ __forceinline__ uint32_t smem_u32(const void* p) {
    uint32_t a;
    asm("{ .reg .u64 t; cvta.to.shared.u64 t, %1; cvt.u32.u64 %0, t; }" : "=r"(a) : "l"(p));
    return a;
}

// ================= preprocessing =================

// Strict sequential fp32 column L1 norms (bit-identical order to passing version).
__global__ void k_colnorm(const float* __restrict__ w) {
    int j = blockIdx.x * 64 + threadIdx.x;
    const float* p = w + j;
    float s = 0.f;
    for (int i = 0; i < DIM_K; i += 32) {
        float v[32];
#pragma unroll
        for (int u = 0; u < 32; ++u) v[u] = fabsf(p[(size_t)(i + u) * DIM_K]);
#pragma unroll
        for (int u = 0; u < 32; ++u) s += v[u];
    }
    g_cn[j] = s;
}

// Single block: bitonic sort, quantiles, band mask, n_bin.
__global__ void k_quant() {
    __shared__ float s_sorted[DIM_K];
    __shared__ float s_lo, s_hi;
    __shared__ int s_cnt;
    int t = threadIdx.x;  // 1024 threads

#pragma unroll
    for (int c = 0; c < 4; ++c) s_sorted[c * 1024 + t] = g_cn[c * 1024 + t];
    if (t == 0) s_cnt = 0;
    __syncthreads();

    for (int k = 2; k <= DIM_K; k <<= 1) {
        for (int jj = k >> 1; jj > 0; jj >>= 1) {
#pragma unroll
            for (int c = 0; c < 4; ++c) {
                int i = c * 1024 + t;
                int ixj = i ^ jj;
                if (ixj > i) {
                    float a = s_sorted[i], b = s_sorted[ixj];
                    bool up = ((i & k) == 0);
                    if ((a > b) == up) { s_sorted[i] = b; s_sorted[ixj] = a; }
                }
            }
            __syncthreads();
        }
    }

    if (t == 0) {
        // jnp.quantile 'linear': 0.05*4095 = 204.75; 0.95*4095 = 3890.25
        s_lo = s_sorted[204]  + 0.75f * (s_sorted[205]  - s_sorted[204]);
        s_hi = s_sorted[3890] + 0.25f * (s_sorted[3891] - s_sorted[3890]);
    }
    __syncthreads();

    int local = 0;
#pragma unroll
    for (int c = 0; c < 4; ++c) {
        int j = c * 1024 + t;
        float v = g_cn[j];
        bool band = (v > s_lo) && (v < s_hi);   // middle band
        float m = band ? 0.f : 1.f;             // binarized = ~band
        g_mask[j] = m;
        local += (int)m;
    }
    atomicAdd(&s_cnt, local);
    __syncthreads();
    if (t == 0) g_nbin = (float)s_cnt;
}

// Per w-row: scale = sum(|w|*mask)/n_bin; o = mask ? w*scale : w; emit fp16.
__global__ void k_wbinh(const float* __restrict__ w) {
    __shared__ float red[256];
    __shared__ float s_scale;
    int r = blockIdx.x, t = threadIdx.x;
    const float* wr = w + (size_t)r * DIM_K;

    float4 v4[4];
#pragma unroll
    for (int c = 0; c < 4; ++c) v4[c] = *(const float4*)(wr + t * 4 + c * 1024);

    float s = 0.f;
#pragma unroll
    for (int c = 0; c < 4; ++c) {
        const float* f = (const float*)&v4[c];
#pragma unroll
        for (int e = 0; e < 4; ++e) s += fabsf(f[e]) * g_mask[t * 4 + c * 1024 + e];
    }
    red[t] = s; __syncthreads();
    for (int o = 128; o > 0; o >>= 1) { if (t < o) red[t] += red[t + o]; __syncthreads(); }
    if (t == 0) s_scale = red[0] / g_nbin;
    __syncthreads();
    float scale = s_scale;

#pragma unroll
    for (int c = 0; c < 4; ++c) {
        const float* f = (const float*)&v4[c];
        float o[4];
#pragma unroll
        for (int e = 0; e < 4; ++e) {
            int j = t * 4 + c * 1024 + e;
            o[e] = (g_mask[j] != 0.f) ? f[e] * scale : f[e];
        }
        size_t idx = (size_t)r * DIM_K + t * 4 + c * 1024;
        *(__half2*)(g_wh + idx)     = __floats2half2_rn(o[0], o[1]);
        *(__half2*)(g_wh + idx + 2) = __floats2half2_rn(o[2], o[3]);
    }
}

// x -> fp16 (RN).
__global__ void k_xhalf(const float* __restrict__ x) {
    size_t i0 = ((size_t)blockIdx.x * 256 + threadIdx.x) * 16;
#pragma unroll
    for (int u = 0; u < 4; ++u) {
        float4 v = *(const float4*)(x + i0 + u * 4);
        *(__half2*)(g_xh + i0 + u * 4)     = __floats2half2_rn(v.x, v.y);
        *(__half2*)(g_xh + i0 + u * 4 + 2) = __floats2half2_rn(v.z, v.w);
    }
}

// ================= GEMM: out = x @ w_bin^T + bias (fp16 mma, f32 accum) =================
// CTA 128x128, BK=64 fp16 (=128B rows, SW128 swizzle). 8 warps (2M x 4N),
// warp tile 64x32. 3-stage cp.async. 2 CTAs/SM.
#define BM 128
#define BN 128
#define BK 64
#define KTILES (DIM_K / BK)         // 64
#define STAGES 3
#define A_BYTES 16384               // 128 rows x 128B
#define B_BYTES 16384
#define STAGE_BYTES (A_BYTES + B_BYTES)
#define GEMM_SMEM (STAGES * STAGE_BYTES)

__device__ __forceinline__ void cp16(uint32_t dst, const void* src) {
    asm volatile("cp.async.cg.shared.global [%0], [%1], 16;" :: "r"(dst), "l"(src));
}
__device__ __forceinline__ void ldm_x4(uint32_t* r, uint32_t addr) {
    asm volatile("ldmatrix.sync.aligned.m8n8.x4.shared.b16 {%0,%1,%2,%3}, [%4];"
                 : "=r"(r[0]), "=r"(r[1]), "=r"(r[2]), "=r"(r[3]) : "r"(addr));
}
__device__ __forceinline__ void mma_f16(float* c, const uint32_t* a,
                                        uint32_t b0, uint32_t b1) {
    asm volatile(
        "mma.sync.aligned.m16n8k16.row.col.f32.f16.f16.f32 "
        "{%0,%1,%2,%3}, {%4,%5,%6,%7}, {%8,%9}, {%0,%1,%2,%3};"
        : "+f"(c[0]), "+f"(c[1]), "+f"(c[2]), "+f"(c[3])
        : "r"(a[0]), "r"(a[1]), "r"(a[2]), "r"(a[3]), "r"(b0), "r"(b1));
}

__global__ void __launch_bounds__(256, 2) k_gemm(
    const float* __restrict__ bias, float* __restrict__ out)
{
    extern __shared__ char smem[];
    const uint32_t sb = smem_u32(smem);
    const int tid = threadIdx.x;
    const int wid = tid >> 5;
    const int lane = tid & 31;
    const int warp_m = wid & 1;    // 0..1 -> M offset 64
    const int warp_n = wid >> 1;   // 0..3 -> N offset 32
    const int ntile = blockIdx.x;
    const int mtile = blockIdx.y;

    const __half* gA = g_xh + (size_t)mtile * BM * DIM_K;
    const __half* gB = g_wh + (size_t)ntile * BN * DIM_K;

    // loaders: 8 threads per 128B smem row (16B each); 4 passes, stride 32 rows
    const int lrow = tid >> 3;          // 0..31
    const int lc   = tid & 7;           // 16B chunk in row
    uint32_t swz[4];
#pragma unroll
    for (int p = 0; p < 4; ++p) {
        int row = lrow + p * 32;
        swz[p] = (uint32_t)(row * 128 + ((lc * 16) ^ ((row & 7) << 4)));
    }

    // ldmatrix lane addressing (identical formulas to proven tf32 version;
    // ks chunk is now 32B = k16 fp16)
    const uint32_t sx = (uint32_t)((lane & 7) << 4);
    const int arow = warp_m * 64 + (lane & 15);                          // + mt*16
    const uint32_t acol16 = (lane & 16) ? 16u : 0u;
    const int brow = warp_n * 32 + (lane & 7) + ((lane & 16) ? 8 : 0);   // + p*16
    const uint32_t bcol16 = (lane & 8) ? 16u : 0u;

    float acc[4][4][4];
#pragma unroll
    for (int i = 0; i < 4; ++i)
#pragma unroll
        for (int j = 0; j < 4; ++j)
#pragma unroll
            for (int k = 0; k < 4; ++k) acc[i][j][k] = 0.f;

    auto load_stage = [&](int s, int kt) {
        uint32_t sA = sb + s * STAGE_BYTES;
        uint32_t sB = sA + A_BYTES;
#pragma unroll
        for (int p = 0; p < 4; ++p) {
            int row = lrow + p * 32;
            cp16(sA + swz[p], gA + (size_t)row * DIM_K + kt * BK + lc * 8);
        }
#pragma unroll
        for (int p = 0; p < 4; ++p) {
            int row = lrow + p * 32;
            cp16(sB + swz[p], gB + (size_t)row * DIM_K + kt * BK + lc * 8);
        }
    };

#pragma unroll
    for (int s = 0; s < STAGES - 1; ++s) {
        load_stage(s, s);
        asm volatile("cp.async.commit_group;" ::: "memory");
    }

    for (int kt = 0; kt < KTILES; ++kt) {
        asm volatile("cp.async.wait_group 1;" ::: "memory");
        __syncthreads();

        if (kt + STAGES - 1 < KTILES) load_stage((kt + STAGES - 1) % STAGES, kt + STAGES - 1);
        asm volatile("cp.async.commit_group;" ::: "memory");

        const int s = kt % STAGES;
        const uint32_t sA = sb + s * STAGE_BYTES;
        const uint32_t sB = sA + A_BYTES;

#pragma unroll
        for (int ks = 0; ks < 4; ++ks) {           // 4 x k16 = BK 64
            uint32_t bfr[8];
#pragma unroll
            for (int p = 0; p < 2; ++p)
                ldm_x4(bfr + 4 * p,
                       sB + (uint32_t)((brow + p * 16) * 128)
                          + (((uint32_t)(ks * 32) + bcol16) ^ sx));
#pragma unroll
            for (int mt = 0; mt < 4; ++mt) {
                uint32_t afr[4];
                ldm_x4(afr, sA + (uint32_t)((arow + mt * 16) * 128)
                              + (((uint32_t)(ks * 32) + acol16) ^ sx));
#pragma unroll
                for (int nt = 0; nt < 4; ++nt)
                    mma_f16(acc[mt][nt], afr, bfr[2 * nt], bfr[2 * nt + 1]);
            }
        }
    }

    // ---- epilogue: add bias, store fp32 ----
    const int obase_n = ntile * BN + warp_n * 32;
    float bv0[4], bv1[4];
#pragma unroll
    for (int nt = 0; nt < 4; ++nt) {
        int col = obase_n + nt * 8 + (lane & 3) * 2;
        bv0[nt] = __ldg(bias + col);
        bv1[nt] = __ldg(bias + col + 1);
    }
#pragma unroll
    for (int mt = 0; mt < 4; ++mt) {
        int row0 = mtile * BM + warp_m * 64 + mt * 16 + (lane >> 2);
#pragma unroll
        for (int nt = 0; nt < 4; ++nt) {
            int col = obase_n + nt * 8 + (lane & 3) * 2;
            float2 o0 = make_float2(acc[mt][nt][0] + bv0[nt], acc[mt][nt][1] + bv1[nt]);
            float2 o1 = make_float2(acc[mt][nt][2] + bv0[nt], acc[mt][nt][3] + bv1[nt]);
            *(float2*)(out + (size_t)row0 * DIM_N + col) = o0;
            *(float2*)(out + (size_t)(row0 + 8) * DIM_N + col) = o1;
        }
    }
}

// ================= launch =================
extern "C" void kernel_launch(void* const* d_in, const int* in_sizes, int n_in,
                              void* d_out, int out_size) {
    const float* x    = (const float*)d_in[0];   // [8192, 4096]
    const float* w    = (const float*)d_in[1];   // [4096, 4096]
    const float* bias = (const float*)d_in[2];   // [4096]
    float* out = (float*)d_out;                  // [8192, 4096]

    cudaFuncSetAttribute(k_gemm, cudaFuncAttributeMaxDynamicSharedMemorySize, GEMM_SMEM);

    k_colnorm<<<DIM_K / 64, 64>>>(w);
    k_quant<<<1, 1024>>>();
    k_wbinh<<<DIM_N, 256>>>(w);
    k_xhalf<<<(size_t)DIM_M * DIM_K / (256 * 16), 256>>>(x);
    k_gemm<<<dim3(DIM_N / BN, DIM_M / BM), 256, GEMM_SMEM>>>(bias, out);
}